// round 15
// baseline (speedup 1.0000x reference)
#include <cuda_runtime.h>
#include <cuda_fp16.h>

#define BATCH 8
#define SEQ   4096
#define HID   1024
#define K1N   33    // Hermitian: store only k1 = 0..32 of 64
#define P1B   512   // pass1 blocks per batch (8 hblk x 64 n2)
#define P2B   264   // pass2 blocks per batch (8 hblk x 33 k1)
#define NBLK  (P1B + P2B)   // 776 blocks per pipeline stage

// Scratch: Y[b][n2][k1(0..32)][h] as half2(re,im): 69 MB total, 8.6 MB/batch.
// The batch handed P1(i) -> P2(i) across one launch boundary stays L2-hot.
__device__ __half2 g_scratch[(size_t)BATCH * 64 * K1N * HID];

// Bit-reverse of 6-bit value (compile-time in unrolled loops)
__device__ __forceinline__ constexpr int rev6(int x) {
    return ((x & 1) << 5) | ((x & 2) << 3) | ((x & 4) << 1) |
           ((x & 8) >> 1) | ((x & 16) >> 3) | ((x & 32) >> 5);
}

// W_64^j, j in [0,32). Literal constants -> FFMA immediates.
__device__ __forceinline__ float tw64_re(int j) {
    constexpr float c[32] = {
        1.00000000000f, 0.99518472667f, 0.98078528040f, 0.95694033573f,
        0.92387953251f, 0.88192126435f, 0.83146961230f, 0.77301045336f,
        0.70710678119f, 0.63439328416f, 0.55557023302f, 0.47139673683f,
        0.38268343236f, 0.29028467725f, 0.19509032202f, 0.09801714033f,
        0.00000000000f,-0.09801714033f,-0.19509032202f,-0.29028467725f,
       -0.38268343236f,-0.47139673683f,-0.55557023302f,-0.63439328416f,
       -0.70710678119f,-0.77301045336f,-0.83146961230f,-0.88192126435f,
       -0.92387953251f,-0.95694033573f,-0.98078528040f,-0.99518472667f };
    return c[j];
}
__device__ __forceinline__ float tw64_im(int j) {
    constexpr float s[32] = {
       -0.00000000000f,-0.09801714033f,-0.19509032202f,-0.29028467725f,
       -0.38268343236f,-0.47139673683f,-0.55557023302f,-0.63439328416f,
       -0.70710678119f,-0.77301045336f,-0.83146961230f,-0.88192126435f,
       -0.92387953251f,-0.95694033573f,-0.98078528040f,-0.99518472667f,
       -1.00000000000f,-0.99518472667f,-0.98078528040f,-0.95694033573f,
       -0.92387953251f,-0.88192126435f,-0.83146961230f,-0.77301045336f,
       -0.70710678119f,-0.63439328416f,-0.55557023302f,-0.47139673683f,
       -0.38268343236f,-0.29028467725f,-0.19509032202f,-0.09801714033f };
    return s[j];
}

// In-register 64-point DIF radix-2 FFT. Output bit-reversed:
// X[k] = re[rev6(k)], im[rev6(k)].
__device__ __forceinline__ void fft64(float (&re)[64], float (&im)[64]) {
#pragma unroll
    for (int stage = 0; stage < 6; stage++) {
        const int s = 32 >> stage;
#pragma unroll
        for (int j = 0; j < 64; j += 2 * s) {
#pragma unroll
            for (int t = 0; t < s; t++) {
                const int a = j + t;
                const int b = a + s;
                float ar = re[a], ai = im[a];
                float br = re[b], bi = im[b];
                re[a] = ar + br;
                im[a] = ai + bi;
                float dr = ar - br, di = ai - bi;
                const int ti = t << stage;
                float wr = tw64_re(ti), wi = tw64_im(ti);
                re[b] = dr * wr - di * wi;
                im[b] = dr * wi + di * wr;
            }
        }
    }
}

// Pipelined stage kernel: P1(batch b1) and P2(batch b2) blocks interleaved in
// one grid. Dependency P1(b) -> P2(b) is carried by the launch boundary of
// sequential same-stream launches; no intra-grid sync, no parked blocks.
// Block-role map (interleaved so wave 1 holds a read+write mix):
//   bid < 528:  even -> P1 sub=bid/2, odd -> P2 sub=bid/2   (P2 subs 0..263)
//   bid >= 528: P1 sub = 264 + (bid - 528)                  (P1 subs 264..511)
__global__ void __launch_bounds__(128)
fft_stage(const float* __restrict__ x, float* __restrict__ out,
          int b1, int b2) {
    const int bid = blockIdx.x;
    int role, sub;
    if (bid < 2 * P2B) { role = (bid & 1) ? 2 : 1; sub = bid >> 1; }
    else               { role = 1; sub = P2B + (bid - 2 * P2B); }

    if (role == 1) {
        if (b1 < 0) return;                 // fill/drain stage: no P1 work
        // ---- Pass 1 (R3 body): FFT64 over n1, twiddle, fp16 scratch ----
        const int h  = (sub & 7) * 128 + threadIdx.x;
        const int n2 = sub >> 3;
        const int b  = b1;

        const float* xp = x + ((size_t)b * SEQ + n2) * HID + h;
        float re[64], im[64];
#pragma unroll
        for (int n1 = 0; n1 < 64; n1++) {
            re[n1] = __ldcs(xp + (size_t)n1 * 64 * HID);  // streaming read
            im[n1] = 0.0f;
        }
        fft64(re, im);

        float bs, bc;
        sincospif(-(float)n2 / 2048.0f, &bs, &bc);  // W_4096^{n2}

        __half2* yp = g_scratch + ((size_t)(b * 64 + n2) * K1N) * HID + h;
        float wr = 1.0f, wi = 0.0f;
#pragma unroll
        for (int k1 = 0; k1 < K1N; k1++) {
            float vr = re[rev6(k1)], vi = im[rev6(k1)];
            yp[(size_t)k1 * HID] = __floats2half2_rn(vr * wr - vi * wi,
                                                     vr * wi + vi * wr);
            float nwr = wr * bc - wi * bs;
            float nwi = wr * bs + wi * bc;
            wr = nwr; wi = nwi;
        }
    } else {
        if (b2 < 0) return;                 // fill stage: no P2 work
        // ---- Pass 2 (R3 body): FFT64 over n2, write Re + mirror row ----
        const int h  = (sub & 7) * 128 + threadIdx.x;
        const int k1 = sub >> 3;            // 0..32
        const int b  = b2;

        const __half2* yp = g_scratch + ((size_t)(b * 64) * K1N + k1) * HID + h;
        float re[64], im[64];
#pragma unroll
        for (int n2 = 0; n2 < 64; n2++) {
            float2 v = __half22float2(yp[(size_t)n2 * K1N * HID]);  // L2 hit
            re[n2] = v.x;
            im[n2] = v.y;
        }
        fft64(re, im);

        float* op = out + ((size_t)b * SEQ) * HID + h;
        const float scale = 1.0f / 64.0f;   // ortho norm 1/sqrt(4096)
#pragma unroll
        for (int k2 = 0; k2 < 64; k2++) {
            __stcs(op + (size_t)(k1 + 64 * k2) * HID, re[rev6(k2)] * scale);
        }
        if (k1 >= 1 && k1 <= 31) {
            const int k1m = 64 - k1;
#pragma unroll
            for (int k2 = 0; k2 < 64; k2++) {
                __stcs(op + (size_t)(k1m + 64 * k2) * HID,
                       re[rev6(63 - k2)] * scale);
            }
        }
    }
}

extern "C" void kernel_launch(void* const* d_in, const int* in_sizes, int n_in,
                              void* d_out, int out_size) {
    const float* x = (const float*)d_in[0];
    float* out = (float*)d_out;

    // Stage i: P1(batch i) + P2(batch i-1). Sequential launches on one stream
    // carry the P1->P2 dependency across the launch boundary.
    for (int i = 0; i <= BATCH; i++) {
        const int b1 = (i < BATCH) ? i : -1;
        const int b2 = (i > 0) ? i - 1 : -1;
        fft_stage<<<NBLK, 128>>>(x, out, b1, b2);
    }
}

// round 17
// speedup vs baseline: 1.4517x; 1.4517x over previous
#include <cuda_runtime.h>
#include <cuda_fp16.h>

#define BATCH 8
#define SEQ   4096
#define HID   1024
#define K1N   33   // Hermitian: store only k1 = 0..32 of 64

// Scratch: Y[b][n2][k1(0..32)][h] as half2(re,im): 69 MB. Mostly L2-resident;
// input/output use streaming (.cs) so scratch stays hot pass1 -> pass2.
__device__ __half2 g_scratch[(size_t)BATCH * 64 * K1N * HID];

// Bit-reverse of 6-bit value (compile-time in unrolled loops)
__device__ __forceinline__ constexpr int rev6(int x) {
    return ((x & 1) << 5) | ((x & 2) << 3) | ((x & 4) << 1) |
           ((x & 8) >> 1) | ((x & 16) >> 3) | ((x & 32) >> 5);
}

// W_64^j, j in [0,32). Literal constants -> FFMA immediates.
__device__ __forceinline__ float tw64_re(int j) {
    constexpr float c[32] = {
        1.00000000000f, 0.99518472667f, 0.98078528040f, 0.95694033573f,
        0.92387953251f, 0.88192126435f, 0.83146961230f, 0.77301045336f,
        0.70710678119f, 0.63439328416f, 0.55557023302f, 0.47139673683f,
        0.38268343236f, 0.29028467725f, 0.19509032202f, 0.09801714033f,
        0.00000000000f,-0.09801714033f,-0.19509032202f,-0.29028467725f,
       -0.38268343236f,-0.47139673683f,-0.55557023302f,-0.63439328416f,
       -0.70710678119f,-0.77301045336f,-0.83146961230f,-0.88192126435f,
       -0.92387953251f,-0.95694033573f,-0.98078528040f,-0.99518472667f };
    return c[j];
}
__device__ __forceinline__ float tw64_im(int j) {
    constexpr float s[32] = {
       -0.00000000000f,-0.09801714033f,-0.19509032202f,-0.29028467725f,
       -0.38268343236f,-0.47139673683f,-0.55557023302f,-0.63439328416f,
       -0.70710678119f,-0.77301045336f,-0.83146961230f,-0.88192126435f,
       -0.92387953251f,-0.95694033573f,-0.98078528040f,-0.99518472667f,
       -1.00000000000f,-0.99518472667f,-0.98078528040f,-0.95694033573f,
       -0.92387953251f,-0.88192126435f,-0.83146961230f,-0.77301045336f,
       -0.70710678119f,-0.63439328416f,-0.55557023302f,-0.47139673683f,
       -0.38268343236f,-0.29028467725f,-0.19509032202f,-0.09801714033f };
    return s[j];
}

// In-register 64-point DIF radix-2 FFT. Output bit-reversed:
// X[k] = re[rev6(k)], im[rev6(k)].
__device__ __forceinline__ void fft64(float (&re)[64], float (&im)[64]) {
#pragma unroll
    for (int stage = 0; stage < 6; stage++) {
        const int s = 32 >> stage;
#pragma unroll
        for (int j = 0; j < 64; j += 2 * s) {
#pragma unroll
            for (int t = 0; t < s; t++) {
                const int a = j + t;
                const int b = a + s;
                float ar = re[a], ai = im[a];
                float br = re[b], bi = im[b];
                re[a] = ar + br;
                im[a] = ai + bi;
                float dr = ar - br, di = ai - bi;
                const int ti = t << stage;
                float wr = tw64_re(ti), wi = tw64_im(ti);
                re[b] = dr * wr - di * wi;
                im[b] = dr * wi + di * wr;
            }
        }
    }
}

// Pass 1 (R3 body, unchanged): per (b, n2, h): A[k1] = FFT64 over n1;
// Y = A[k1] * W_4096^{n2*k1}, fp16, k1 = 0..32.
__global__ void __launch_bounds__(128) fft_pass1(const float* __restrict__ x) {
    const int h  = blockIdx.x * 128 + threadIdx.x;  // HID/128 = 8
    const int n2 = blockIdx.y;                      // 64
    const int b  = blockIdx.z;                      // 8

    const float* xp = x + ((size_t)b * SEQ + n2) * HID + h;
    float re[64], im[64];
#pragma unroll
    for (int n1 = 0; n1 < 64; n1++) {
        re[n1] = __ldcs(xp + (size_t)n1 * 64 * HID);  // streaming read
        im[n1] = 0.0f;
    }
    fft64(re, im);

    float bs, bc;
    sincospif(-(float)n2 / 2048.0f, &bs, &bc);  // W_4096^{n2}

    __half2* yp = g_scratch + ((size_t)(b * 64 + n2) * K1N) * HID + h;
    float wr = 1.0f, wi = 0.0f;
#pragma unroll
    for (int k1 = 0; k1 < K1N; k1++) {
        float vr = re[rev6(k1)], vi = im[rev6(k1)];
        yp[(size_t)k1 * HID] = __floats2half2_rn(vr * wr - vi * wi,
                                                 vr * wi + vi * wr);
        float nwr = wr * bc - wi * bs;
        float nwi = wr * bs + wi * bc;
        wr = nwr; wi = nwi;
    }
}

// Pass 2 with Hermitian-output pairing: one FFT64 serves TWO k1 columns.
// Re(FFT(Y)) = FFT(H(Y)), H(Y)[n] = 0.5*(Y[n] + conj(Y[(64-n)%64])) is
// Hermitian -> real spectrum. z = H(Ya) + i*H(Yb) => FFT(z).re = out_a,
// FFT(z).im = out_b. Pairs: p=0 -> (0,32); p=1..15 -> (p, 32-p); p=16 -> k1=16
// single (classic path). Mirror rows as before.
__global__ void __launch_bounds__(128) fft_pass2(float* __restrict__ out) {
    const int h = blockIdx.x * 128 + threadIdx.x;
    const int p = blockIdx.y;                       // 0..16
    const int b = blockIdx.z;

    float* op = out + ((size_t)b * SEQ) * HID + h;
    const float scale = 1.0f / 64.0f;  // ortho norm 1/sqrt(4096)
    const size_t n_stride = (size_t)K1N * HID;
    const __half2* base = g_scratch + ((size_t)(b * 64) * K1N) * HID + h;

    if (p < 16) {
        const int ka = p;                 // 0..15
        const int kb = 32 - p;            // 32..17
        const __half2* yA = base + (size_t)ka * HID;   // column ka
        const __half2* yB = base + (size_t)kb * HID;   // column kb

        float re[64], im[64];
#pragma unroll
        for (int n = 0; n <= 32; n++) {
            const int m = (64 - n) & 63;
            float2 an = __half22float2(yA[(size_t)n * n_stride]);
            float2 am = __half22float2(yA[(size_t)m * n_stride]);
            float2 bn = __half22float2(yB[(size_t)n * n_stride]);
            float2 bm = __half22float2(yB[(size_t)m * n_stride]);
            // z[n] = H(Ya)[n] + i*H(Yb)[n]
            re[n] = 0.5f * (an.x + am.x) - 0.5f * (bn.y - bm.y);
            im[n] = 0.5f * (an.y - am.y) + 0.5f * (bn.x + bm.x);
            if (n != 0 && n != 32) {
                re[m] = 0.5f * (am.x + an.x) - 0.5f * (bm.y - bn.y);
                im[m] = 0.5f * (am.y - an.y) + 0.5f * (bm.x + bn.x);
            }
        }
        fft64(re, im);

        const bool mirror = (p >= 1);     // ka in 1..15, kb in 17..31
#pragma unroll
        for (int k2 = 0; k2 < 64; k2++) {
            const float va = re[rev6(k2)] * scale;   // out row ka
            const float vb = im[rev6(k2)] * scale;   // out row kb
            __stcs(op + (size_t)(ka + 64 * k2) * HID, va);
            __stcs(op + (size_t)(kb + 64 * k2) * HID, vb);
            if (mirror) {
                // Re X[(64-k)+64*k2] = Re X[k+64*(63-k2)]
                __stcs(op + (size_t)((64 - ka) + 64 * (63 - k2)) * HID, va);
                __stcs(op + (size_t)((64 - kb) + 64 * (63 - k2)) * HID, vb);
            }
        }
    } else {
        // k1 = 16 single column (classic R3 path) + mirror row 48
        const int k1 = 16;
        const __half2* yp = base + (size_t)k1 * HID;
        float re[64], im[64];
#pragma unroll
        for (int n2 = 0; n2 < 64; n2++) {
            float2 v = __half22float2(yp[(size_t)n2 * n_stride]);
            re[n2] = v.x;
            im[n2] = v.y;
        }
        fft64(re, im);
#pragma unroll
        for (int k2 = 0; k2 < 64; k2++) {
            __stcs(op + (size_t)(k1 + 64 * k2) * HID, re[rev6(k2)] * scale);
            __stcs(op + (size_t)(48 + 64 * (63 - k2)) * HID, re[rev6(k2)] * scale);
        }
    }
}

extern "C" void kernel_launch(void* const* d_in, const int* in_sizes, int n_in,
                              void* d_out, int out_size) {
    const float* x = (const float*)d_in[0];
    float* out = (float*)d_out;

    fft_pass1<<<dim3(HID / 128, 64, BATCH), 128>>>(x);
    fft_pass2<<<dim3(HID / 128, 17, BATCH), 128>>>(out);
}